// round 3
// baseline (speedup 1.0000x reference)
#include <cuda_runtime.h>
#include <cstdint>
#include <math.h>

typedef unsigned long long ULL;

// ---- problem dims ----
#define B_    32
#define D_    64
#define K_    26
#define QST_  256
#define H_    512
#define NANS  28

#define TILE_M 64    // pair rows per CTA (q index)
#define KB     16    // k-chunk per weight stage

// ---- device scratch (no allocation allowed) ----
__device__ float g_u[B_ * D_ * H_];     // W0[:, :26] @ x  (per object)     4 MB
__device__ float g_v[B_ * D_ * H_];     // W0[:, 26:] @ x + b0              4 MB
__device__ float g_Wt[3 * H_ * H_];     // W1..W3 transposed: [l][k][o]     3 MB
__device__ float g_part[B_ * D_ * H_];  // per-(b,p) partial row sums       4 MB

// ---- helpers ----
__device__ __forceinline__ void cpasync16(void* smem, const void* g) {
    unsigned s = (unsigned)__cvta_generic_to_shared(smem);
    asm volatile("cp.async.cg.shared.global [%0], [%1], 16;" :: "r"(s), "l"(g));
}
__device__ __forceinline__ void cpasync_commit() {
    asm volatile("cp.async.commit_group;" ::: "memory");
}

// =====================================================================
// Prep 1: per-object projections u, v (folds layer 0's GEMM: 64x cheaper)
// grid = B_, block = 512 (thread = output channel)
// =====================================================================
__global__ void prep_uv(const float* __restrict__ x,
                        const float* __restrict__ W0,
                        const float* __restrict__ b0) {
    extern __shared__ float sm[];
    float* Ws = sm;                 // 512*52
    float* xs = sm + H_ * 52;       // 64*26
    int b = blockIdx.x;
    int tid = threadIdx.x;
    for (int i = tid; i < H_ * 52; i += blockDim.x) Ws[i] = W0[i];
    for (int i = tid; i < D_ * K_; i += blockDim.x) xs[i] = x[b * D_ * K_ + i];
    __syncthreads();
    float bb = b0[tid];
    const float* w = Ws + tid * 52;
    for (int o = 0; o < D_; ++o) {
        const float* xo = xs + o * K_;
        float u = 0.f, v = 0.f;
#pragma unroll
        for (int j = 0; j < K_; ++j) {
            u = fmaf(w[j],      xo[j], u);
            v = fmaf(w[26 + j], xo[j], v);
        }
        g_u[(b * D_ + o) * H_ + tid] = u;
        g_v[(b * D_ + o) * H_ + tid] = v + bb;
    }
}

// =====================================================================
// Prep 2: transpose W1..W3 -> [k][o] so the main kernel's weight loads
// are fully coalesced. grid = (16,16,3), block = (32,8)
// =====================================================================
__global__ void prep_transpose(const float* __restrict__ W1,
                               const float* __restrict__ W2,
                               const float* __restrict__ W3) {
    __shared__ float tile[32][33];
    int l = blockIdx.z;
    const float* W = (l == 0) ? W1 : ((l == 1) ? W2 : W3);
    float* out = g_Wt + l * H_ * H_;
    int x0 = blockIdx.x * 32, y0 = blockIdx.y * 32;
    int tx = threadIdx.x, ty = threadIdx.y;
#pragma unroll
    for (int i = 0; i < 32; i += 8)
        tile[ty + i][tx] = W[(y0 + ty + i) * H_ + x0 + tx];   // W[o][k], k coalesced
    __syncthreads();
#pragma unroll
    for (int i = 0; i < 32; i += 8)
        out[(x0 + ty + i) * H_ + y0 + tx] = tile[tx][ty + i]; // Wt[k][o], o coalesced
}

// =====================================================================
// Main: fused layer0 + 3x(512x512 GEMM + relu) + row-sum partials.
// grid = (D_, B_): CTA owns pairs (p=blockIdx.x, q=0..63) of batch b.
// Activations [64x512] stay in SMEM the whole time; weights stream
// via cp.async double buffer. Inner loop uses packed fma.rn.f32x2.
// SMEM: 64*512*4 + 2*16*512*4 = 196608 B.
// =====================================================================
__global__ __launch_bounds__(512, 1)
void rn_pair_kernel(const float* __restrict__ b1,
                    const float* __restrict__ b2,
                    const float* __restrict__ b3) {
    extern __shared__ float sm[];
    float* As = sm;                        // [64][512]
    float* Bs = sm + TILE_M * H_;          // 2 x [KB][512]

    const int p   = blockIdx.x;
    const int b   = blockIdx.y;
    const int tid = threadIdx.x;
    const int rg  = tid >> 6;              // 0..7  (row group)
    const int cg  = tid & 63;              // 0..63 (col group)
    const int r0  = rg * 8;
    const int o0  = cg * 8;

    // ---- layer 0: As[q][c] = relu(u[b,q,c] + v[b,p,c]) ----
    const float* ub = g_u + (b * D_) * H_;
    const float* vb = g_v + (b * D_ + p) * H_;
    for (int i = tid; i < TILE_M * H_; i += 512) {
        int r = i >> 9, c = i & 511;
        float t = ub[r * H_ + c] + vb[c];
        As[i] = t > 0.f ? t : 0.f;
    }
    // (visibility of As is guaranteed by the barrier before the first compute)

    for (int l = 0; l < 3; ++l) {
        const float* W    = g_Wt + l * H_ * H_;
        const float* bias = (l == 0) ? b1 : ((l == 1) ? b2 : b3);

        // accumulators initialized with bias (packed f32x2: lo=o0+2j, hi=o0+2j+1)
        ULL acc[8][4];
        {
            unsigned blo[4], bhi[4];
#pragma unroll
            for (int j = 0; j < 4; ++j) {
                blo[j] = __float_as_uint(bias[o0 + 2 * j]);
                bhi[j] = __float_as_uint(bias[o0 + 2 * j + 1]);
            }
#pragma unroll
            for (int i = 0; i < 8; ++i)
#pragma unroll
                for (int j = 0; j < 4; ++j)
                    asm("mov.b64 %0, {%1,%2};" : "=l"(acc[i][j]) : "r"(blo[j]), "r"(bhi[j]));
        }

        // prefetch chunk 0 (each thread: 4x 16B, coalesced)
        {
            float* dst = Bs;
            const float* src = W;
#pragma unroll
            for (int q = 0; q < 4; ++q)
                cpasync16(dst + 4 * (tid + 512 * q), src + 4 * (tid + 512 * q));
            cpasync_commit();
        }

        for (int c = 0; c < H_ / KB; ++c) {
            if (c + 1 < H_ / KB) {
                // buffer (c+1)&1 was released by the barrier ending iteration c-1
                float* dst = Bs + ((c + 1) & 1) * (KB * H_);
                const float* src = W + (c + 1) * KB * H_;
#pragma unroll
                for (int q = 0; q < 4; ++q)
                    cpasync16(dst + 4 * (tid + 512 * q), src + 4 * (tid + 512 * q));
                cpasync_commit();
                asm volatile("cp.async.wait_group 1;" ::: "memory");
            } else {
                asm volatile("cp.async.wait_group 0;" ::: "memory");
            }
            __syncthreads();   // chunk c visible to all; As (layer input) visible

            const float* Bc   = Bs + (c & 1) * (KB * H_);
            const float* Arow = As + r0 * H_ + c * KB;
#pragma unroll
            for (int kk = 0; kk < KB; ++kk) {
                ULL a2[8];
#pragma unroll
                for (int i = 0; i < 8; ++i) {
                    unsigned ai = __float_as_uint(Arow[i * H_ + kk]);  // warp-broadcast LDS
                    asm("mov.b64 %0, {%1,%1};" : "=l"(a2[i]) : "r"(ai));
                }
                const ULL* bp = (const ULL*)(Bc + kk * H_ + o0);       // LDS.64, conflict-free
                ULL bv[4];
#pragma unroll
                for (int j = 0; j < 4; ++j) bv[j] = bp[j];
#pragma unroll
                for (int i = 0; i < 8; ++i)
#pragma unroll
                    for (int j = 0; j < 4; ++j)
                        asm("fma.rn.f32x2 %0, %1, %2, %0;"
                            : "+l"(acc[i][j]) : "l"(a2[i]), "l"(bv[j]));
            }
            __syncthreads();   // done reading this buffer before next overwrite
        }

        // epilogue: relu, write back into As (safe: barrier above drained all readers)
#pragma unroll
        for (int i = 0; i < 8; ++i)
#pragma unroll
            for (int j = 0; j < 4; ++j) {
                unsigned lo, hi;
                asm("mov.b64 {%0,%1}, %2;" : "=r"(lo), "=r"(hi) : "l"(acc[i][j]));
                float flo = __uint_as_float(lo), fhi = __uint_as_float(hi);
                flo = flo > 0.f ? flo : 0.f;
                fhi = fhi > 0.f ? fhi : 0.f;
                As[(r0 + i) * H_ + o0 + 2 * j]     = flo;
                As[(r0 + i) * H_ + o0 + 2 * j + 1] = fhi;
            }
        // next layer's pre-compute barrier orders these writes
    }

    // ---- deterministic aggregation: column sums of this CTA's 64 rows ----
    __syncthreads();
    float s = 0.f;
#pragma unroll 8
    for (int r = 0; r < TILE_M; ++r) s += As[r * H_ + tid];
    g_part[(b * D_ + p) * H_ + tid] = s;
}

// =====================================================================
// Head: reduce partials, concat qst, layers 4-6, log_softmax.
// grid = B_, block = 256 (8 warps; warp-cooperative coalesced dots)
// =====================================================================
__global__ void rn_head_kernel(const float* __restrict__ qst,
                               const float* __restrict__ W4, const float* __restrict__ b4,
                               const float* __restrict__ W5, const float* __restrict__ b5,
                               const float* __restrict__ W6, const float* __restrict__ b6,
                               float* __restrict__ out) {
    __shared__ float hin[H_ + QST_];
    __shared__ float h4[H_];
    __shared__ float h5[H_];
    __shared__ float logits[NANS];
    const int b = blockIdx.x;
    const int tid = threadIdx.x;
    const int w = tid >> 5, lane = tid & 31;

    for (int c = tid; c < H_; c += 256) {
        float s = 0.f;
        const float* pp = g_part + b * D_ * H_ + c;
#pragma unroll 8
        for (int p = 0; p < D_; ++p) s += pp[p * H_];
        hin[c] = s;
    }
    if (tid < QST_) hin[H_ + tid] = qst[b * QST_ + tid];
    __syncthreads();

    for (int o = w; o < H_; o += 8) {                 // layer 4: 768 -> 512
        const float* wr = W4 + o * (H_ + QST_);
        float a = 0.f;
        for (int j = lane; j < H_ + QST_; j += 32) a = fmaf(wr[j], hin[j], a);
#pragma unroll
        for (int off = 16; off; off >>= 1) a += __shfl_xor_sync(0xffffffffu, a, off);
        if (lane == 0) { float t = a + b4[o]; h4[o] = t > 0.f ? t : 0.f; }
    }
    __syncthreads();

    for (int o = w; o < H_; o += 8) {                 // layer 5: 512 -> 512
        const float* wr = W5 + o * H_;
        float a = 0.f;
        for (int j = lane; j < H_; j += 32) a = fmaf(wr[j], h4[j], a);
#pragma unroll
        for (int off = 16; off; off >>= 1) a += __shfl_xor_sync(0xffffffffu, a, off);
        if (lane == 0) { float t = a + b5[o]; h5[o] = t > 0.f ? t : 0.f; }
    }
    __syncthreads();

    for (int o = w; o < NANS; o += 8) {               // layer 6: 512 -> 28
        const float* wr = W6 + o * H_;
        float a = 0.f;
        for (int j = lane; j < H_; j += 32) a = fmaf(wr[j], h5[j], a);
#pragma unroll
        for (int off = 16; off; off >>= 1) a += __shfl_xor_sync(0xffffffffu, a, off);
        if (lane == 0) logits[o] = a + b6[o];
    }
    __syncthreads();

    if (w == 0) {                                     // log_softmax over 28
        float z = lane < NANS ? logits[lane] : -INFINITY;
        float m = z;
#pragma unroll
        for (int off = 16; off; off >>= 1) m = fmaxf(m, __shfl_xor_sync(0xffffffffu, m, off));
        float e = lane < NANS ? expf(z - m) : 0.f;
        float s = e;
#pragma unroll
        for (int off = 16; off; off >>= 1) s += __shfl_xor_sync(0xffffffffu, s, off);
        if (lane < NANS) out[b * NANS + lane] = z - m - logf(s);
    }
}

// =====================================================================
extern "C" void kernel_launch(void* const* d_in, const int* in_sizes, int n_in,
                              void* d_out, int out_size) {
    const float* x   = (const float*)d_in[0];
    const float* qst = (const float*)d_in[1];
    const float* W0  = (const float*)d_in[2];
    const float* b0  = (const float*)d_in[3];
    const float* W1  = (const float*)d_in[4];
    const float* b1  = (const float*)d_in[5];
    const float* W2  = (const float*)d_in[6];
    const float* b2  = (const float*)d_in[7];
    const float* W3  = (const float*)d_in[8];
    const float* b3  = (const float*)d_in[9];
    const float* W4  = (const float*)d_in[10];
    const float* b4  = (const float*)d_in[11];
    const float* W5  = (const float*)d_in[12];
    const float* b5  = (const float*)d_in[13];
    const float* W6  = (const float*)d_in[14];
    const float* b6  = (const float*)d_in[15];
    float* out = (float*)d_out;

    const int smem_uv   = (H_ * 52 + D_ * K_) * 4;                 // 113152
    const int smem_main = (TILE_M * H_ + 2 * KB * H_) * 4;         // 196608
    cudaFuncSetAttribute(prep_uv,        cudaFuncAttributeMaxDynamicSharedMemorySize, smem_uv);
    cudaFuncSetAttribute(rn_pair_kernel, cudaFuncAttributeMaxDynamicSharedMemorySize, smem_main);

    prep_uv<<<B_, 512, smem_uv>>>(x, W0, b0);
    prep_transpose<<<dim3(16, 16, 3), dim3(32, 8)>>>(W1, W2, W3);
    rn_pair_kernel<<<dim3(D_, B_), 512, smem_main>>>(b1, b2, b3);
    rn_head_kernel<<<B_, 256>>>(qst, W4, b4, W5, b5, W6, b6, out);
}

// round 7
// speedup vs baseline: 3.1771x; 3.1771x over previous
#include <cuda_runtime.h>
#include <cuda_fp16.h>
#include <cstdint>
#include <math.h>

typedef unsigned int U32;
typedef unsigned long long ULL;

#define B_    32
#define D_    64
#define K_    26
#define QST_  256
#define H_    512
#define NANS  28

// ---- pair-kernel SMEM map (bytes) ----
#define AOFF      0          // A: 128 rows x 512 fp16, row stride 1024B, XOR swizzle (128KB)
#define WOFF      131072     // 2 stages x 32KB weight chunks
#define BIASOFF   196608     // 512 floats
#define SMEM_PAIR 198656

// ---- device scratch ----
__device__ float  g_u[B_ * D_ * H_];
__device__ float  g_v[B_ * D_ * H_];
__device__ float  g_part[B_ * D_ * H_];
// weights, ldmatrix-ready: block = [l(3)][nch(2)][kc(16)][term(2)][ks(2)] of 8KB
__device__ __half g_Wh[3 * 2 * 16 * 2 * 2 * 4096];
// chunk-0 activation stash: [cta(1024)][tid(512)][8 x uint4]
__device__ uint4  g_stash[1024 * 512 * 8];

// =====================================================================
// helpers
// =====================================================================
__device__ __forceinline__ U32 smem_u32(const void* p) {
    U32 a;
    asm("{ .reg .u64 t; cvta.to.shared.u64 t, %1; cvt.u32.u64 %0, t; }" : "=r"(a) : "l"(p));
    return a;
}
__device__ __forceinline__ void cpasync16(U32 smem, const void* g) {
    asm volatile("cp.async.cg.shared.global [%0], [%1], 16;" :: "r"(smem), "l"(g));
}
#define CP_COMMIT() asm volatile("cp.async.commit_group;" ::: "memory")
#define CP_WAIT1()  asm volatile("cp.async.wait_group 1;" ::: "memory")
#define CP_WAIT0()  asm volatile("cp.async.wait_group 0;" ::: "memory")

__device__ __forceinline__ void ldm_x4(U32& r0, U32& r1, U32& r2, U32& r3, U32 addr) {
    asm volatile("ldmatrix.sync.aligned.m8n8.x4.shared.b16 {%0,%1,%2,%3}, [%4];"
                 : "=r"(r0), "=r"(r1), "=r"(r2), "=r"(r3) : "r"(addr));
}
__device__ __forceinline__ void mma16816(float& d0, float& d1, float& d2, float& d3,
                                         U32 a0, U32 a1, U32 a2, U32 a3, U32 b0, U32 b1) {
    asm volatile("mma.sync.aligned.m16n8k16.row.col.f32.f16.f16.f32 "
                 "{%0,%1,%2,%3}, {%4,%5,%6,%7}, {%8,%9}, {%0,%1,%2,%3};"
                 : "+f"(d0), "+f"(d1), "+f"(d2), "+f"(d3)
                 : "r"(a0), "r"(a1), "r"(a2), "r"(a3), "r"(b0), "r"(b1));
}
__device__ __forceinline__ U32 pack_h2(float a, float b) {
    return (U32)__half_as_ushort(__float2half_rn(a)) |
           ((U32)__half_as_ushort(__float2half_rn(b)) << 16);
}
// A-tile store/load address: row stride 1024B, XOR bits[4:6] with (row&7)<<4
__device__ __forceinline__ U32 a_addr(U32 smem, int row, U32 colbyte) {
    return smem + AOFF + (U32)row * 1024u + (colbyte ^ (U32)((row & 7) << 4));
}
__device__ __forceinline__ void stsh32(U32 addr, U32 v) {
    asm volatile("st.shared.b32 [%0], %1;" :: "r"(addr), "r"(v) : "memory");
}

// =====================================================================
// Prep 1: per-object projections u, v (folds layer 0: 64x cheaper)
// =====================================================================
__global__ void prep_uv(const float* __restrict__ x,
                        const float* __restrict__ W0,
                        const float* __restrict__ b0) {
    extern __shared__ float smf[];
    float* Ws = smf;
    float* xs = smf + H_ * 52;
    int b = blockIdx.x, tid = threadIdx.x;
    for (int i = tid; i < H_ * 52; i += blockDim.x) Ws[i] = W0[i];
    for (int i = tid; i < D_ * K_; i += blockDim.x) xs[i] = x[b * D_ * K_ + i];
    __syncthreads();
    float bb = b0[tid];
    const float* w = Ws + tid * 52;
    for (int o = 0; o < D_; ++o) {
        const float* xo = xs + o * K_;
        float u = 0.f, v = 0.f;
#pragma unroll
        for (int j = 0; j < K_; ++j) {
            u = fmaf(w[j],      xo[j], u);
            v = fmaf(w[26 + j], xo[j], v);
        }
        g_u[(b * D_ + o) * H_ + tid] = u;
        g_v[(b * D_ + o) * H_ + tid] = v + bb;
    }
}

// =====================================================================
// Prep 2: split W1..W3 into fp16 hi/lo, ldmatrix-ready swizzled blocks.
// layout: block(l,nch,kc,term,ks) of 8KB = 256 n-rows x 32B (2x16B k-halves),
// byte in block = ((nr*32 + kpart*16) ^ (((nr>>2)&1)<<4)) + (kk&7)*2
// =====================================================================
__global__ void prep_w(const float* __restrict__ W1,
                       const float* __restrict__ W2,
                       const float* __restrict__ W3) {
    int idx = blockIdx.x * blockDim.x + threadIdx.x;
    if (idx >= 3 * H_ * H_) return;
    int l = idx / (H_ * H_);
    int rem = idx - l * H_ * H_;
    int n = rem >> 9, k = rem & 511;
    const float* W = (l == 0) ? W1 : ((l == 1) ? W2 : W3);
    float w = W[n * H_ + k];
    __half hi = __float2half_rn(w);
    __half lo = __float2half_rn(w - __half2float(hi));
    int nch = n >> 8, nr = n & 255;
    int kc = k >> 5, ks = (k >> 4) & 1, kk = k & 15;
    U32 inner = (U32)((nr * 32 + ((kk >> 3) << 4)) ^ (((nr >> 2) & 1) << 4)) + (U32)((kk & 7) * 2);
    size_t blk = ((((size_t)l * 2 + nch) * 16 + kc) * 2);
    __half* base = g_Wh + (blk * 2) * 4096;
    *(__half*)((char*)base + (size_t)(0 * 2 + ks) * 8192 + inner) = hi;
    *(__half*)((char*)base + (size_t)(1 * 2 + ks) * 8192 + inner) = lo;
}

// =====================================================================
// Main pair kernel: HMMA fused layer0 + 3x(512x512) + aggregation.
// grid = (32, 32): p0 = 2*blockIdx.x, b = blockIdx.y. 512 threads.
// =====================================================================
__global__ __launch_bounds__(512, 1)
void rn_pair_kernel(const float* __restrict__ b1,
                    const float* __restrict__ b2,
                    const float* __restrict__ b3) {
    extern __shared__ __align__(16) char smc[];
    const U32 smem = smem_u32(smc);
    float* bsm = (float*)(smc + BIASOFF);
    const int tid = threadIdx.x;
    const int wid = tid >> 5, lane = tid & 31;
    const int rg = wid & 7, cg = wid >> 3;          // 8 row groups x 2 col groups
    const int b = blockIdx.y;
    const int p0 = blockIdx.x * 2;
    const int cta = b * 32 + blockIdx.x;

    // ---- layer 0 fill: A[r][c] = fp16(relu(u[b, r&63, c] + v[b, p0+(r>>6), c])) ----
    {
        const int r = tid >> 2, qd = tid & 3;
        const int q = r & 63, p = p0 + (r >> 6);
        const float4* u4 = (const float4*)(g_u + (size_t)(b * D_ + q) * H_);
        const float4* v4 = (const float4*)(g_v + (size_t)(b * D_ + p) * H_);
#pragma unroll 4
        for (int it = 0; it < 16; ++it) {
            int c4 = qd * 32 + it * 2;
            float4 ua = u4[c4], ub = u4[c4 + 1], va = v4[c4], vb = v4[c4 + 1];
            float t0 = fmaxf(ua.x + va.x, 0.f), t1 = fmaxf(ua.y + va.y, 0.f);
            float t2 = fmaxf(ua.z + va.z, 0.f), t3 = fmaxf(ua.w + va.w, 0.f);
            float t4 = fmaxf(ub.x + vb.x, 0.f), t5 = fmaxf(ub.y + vb.y, 0.f);
            float t6 = fmaxf(ub.z + vb.z, 0.f), t7 = fmaxf(ub.w + vb.w, 0.f);
            U32 p0w = pack_h2(t0, t1), p1w = pack_h2(t2, t3);
            U32 p2w = pack_h2(t4, t5), p3w = pack_h2(t6, t7);
            U32 addr = a_addr(smem, r, (U32)(qd * 256 + it * 16));
            asm volatile("st.shared.v4.b32 [%0], {%1,%2,%3,%4};"
                         :: "r"(addr), "r"(p0w), "r"(p1w), "r"(p2w), "r"(p3w) : "memory");
        }
    }

    // per-thread invariant ldmatrix address parts
    const int arow = rg * 16 + (lane & 15);                 // A frag row for this lane
    const U32 arsw = (U32)((arow & 7) << 4);
    const U32 arbase = smem + AOFF + (U32)arow * 1024u;
    const U32 al16 = (U32)(lane & 16);                      // +16B for k+8 halves
    const int bd = (lane & 7) + ((lane & 16) >> 1);         // B frag n-row within pair
    // *** FIX: col-group selects its 128-row half of the 256-row weight block ***
    const U32 bT = (U32)(cg * 4096) +
                   (U32)((bd * 32 + (((lane >> 3) & 1) << 4)) ^ (((bd >> 2) & 1) << 4));

    for (int l = 0; l < 3; ++l) {
        const float* bias = (l == 0) ? b1 : ((l == 1) ? b2 : b3);
        bsm[tid] = bias[tid];
        __syncthreads();                                    // bias + A visible

        for (int nch = 0; nch < 2; ++nch) {
            const char* wsrc = (const char*)g_Wh + (((size_t)l * 2 + nch) * 16) * 32768;

            float acc[16][4];
#pragma unroll
            for (int f = 0; f < 16; ++f) {
                acc[f][0] = 0.f; acc[f][1] = 0.f; acc[f][2] = 0.f; acc[f][3] = 0.f;
            }

            // prefetch kc 0
            {
                U32 d = smem + WOFF + (U32)tid * 16;
#pragma unroll
                for (int j = 0; j < 4; ++j)
                    cpasync16(d + j * 8192, wsrc + tid * 16 + j * 8192);
                CP_COMMIT();
            }

            for (int kc = 0; kc < 16; ++kc) {
                if (kc + 1 < 16) {
                    U32 d = smem + WOFF + (U32)(((kc + 1) & 1) * 32768) + (U32)tid * 16;
                    const char* s = wsrc + (size_t)(kc + 1) * 32768 + tid * 16;
#pragma unroll
                    for (int j = 0; j < 4; ++j)
                        cpasync16(d + j * 8192, s + j * 8192);
                    CP_COMMIT();
                    CP_WAIT1();
                } else {
                    CP_WAIT0();
                }
                __syncthreads();

                const U32 wb = smem + WOFF + (U32)((kc & 1) * 32768);
#pragma unroll
                for (int ks = 0; ks < 2; ++ks) {
                    // A fragment (shared between hi and lo terms)
                    U32 cb = (U32)(kc * 64 + ks * 32) + al16;
                    U32 a0, a1, a2, a3;
                    ldm_x4(a0, a1, a2, a3, arbase + (cb ^ arsw));
#pragma unroll
                    for (int t = 0; t < 2; ++t) {
                        const U32 bb = wb + (U32)((t * 2 + ks) * 8192) + bT;
#pragma unroll
                        for (int fp = 0; fp < 8; ++fp) {
                            U32 b0, b1, b2c, b3c;
                            ldm_x4(b0, b1, b2c, b3c, bb + (U32)(fp * 512));
                            mma16816(acc[2*fp][0], acc[2*fp][1], acc[2*fp][2], acc[2*fp][3],
                                     a0, a1, a2, a3, b0, b1);
                            mma16816(acc[2*fp+1][0], acc[2*fp+1][1], acc[2*fp+1][2], acc[2*fp+1][3],
                                     a0, a1, a2, a3, b2c, b3c);
                        }
                    }
                }
                __syncthreads();   // buffer fully consumed before next overwrite
            }

            // ---- epilogue: +bias, relu, pack fp16 pairs ----
            U32 pk[32];
#pragma unroll
            for (int f = 0; f < 16; ++f) {
                int nc = nch * 256 + cg * 128 + f * 8 + ((lane & 3) << 1);
                float bx = bsm[nc], by = bsm[nc + 1];
                float v0 = fmaxf(acc[f][0] + bx, 0.f);
                float v1 = fmaxf(acc[f][1] + by, 0.f);
                float v2 = fmaxf(acc[f][2] + bx, 0.f);
                float v3 = fmaxf(acc[f][3] + by, 0.f);
                pk[2 * f]     = pack_h2(v0, v1);
                pk[2 * f + 1] = pack_h2(v2, v3);
            }

            if (nch == 0) {
                // stash chunk-0 output per-thread-contiguous in global scratch
                uint4* dst = g_stash + ((size_t)cta * 512 + tid) * 8;
#pragma unroll
                for (int j = 0; j < 8; ++j)
                    dst[j] = make_uint4(pk[4*j], pk[4*j+1], pk[4*j+2], pk[4*j+3]);
            } else {
                // chunk-1 -> A[:,256:512]
                const int rA = rg * 16 + (lane >> 2);
#pragma unroll
                for (int f = 0; f < 16; ++f) {
                    int nc = 256 + cg * 128 + f * 8 + ((lane & 3) << 1);
                    stsh32(a_addr(smem, rA,     (U32)(nc * 2)), pk[2*f]);
                    stsh32(a_addr(smem, rA + 8, (U32)(nc * 2)), pk[2*f+1]);
                }
                // chunk-0 stash -> A[:,0:256]  (own data; no fence needed)
                const uint4* src = g_stash + ((size_t)cta * 512 + tid) * 8;
#pragma unroll
                for (int j = 0; j < 8; ++j) {
                    uint4 s = src[j];
                    U32 q0[4] = { s.x, s.y, s.z, s.w };
#pragma unroll
                    for (int c = 0; c < 4; ++c) {
                        int i = j * 4 + c, f = i >> 1, h = i & 1;
                        int nc = cg * 128 + f * 8 + ((lane & 3) << 1);
                        stsh32(a_addr(smem, rA + h * 8, (U32)(nc * 2)), q0[c]);
                    }
                }
                __syncthreads();   // A complete before next layer / aggregation
            }
        }
    }

    // ---- deterministic aggregation: per (p-half, col-pair) sums over 64 rows ----
    {
        const int g = tid >> 8, c2 = (tid & 255) * 2;
        float s0 = 0.f, s1 = 0.f;
#pragma unroll 8
        for (int rr = 0; rr < 64; ++rr) {
            int r = g * 64 + rr;
            U32 h2;
            asm volatile("ld.shared.b32 %0, [%1];" : "=r"(h2)
                         : "r"(a_addr(smem, r, (U32)(c2 * 2))));
            s0 += __half2float(__ushort_as_half((unsigned short)(h2 & 0xffff)));
            s1 += __half2float(__ushort_as_half((unsigned short)(h2 >> 16)));
        }
        g_part[((size_t)b * D_ + p0 + g) * H_ + c2]     = s0;
        g_part[((size_t)b * D_ + p0 + g) * H_ + c2 + 1] = s1;
    }
}

// =====================================================================
// Head: reduce partials, concat qst, layers 4-6, log_softmax.
// grid = 32, block = 1024 (32 warps, float4 warp-dots).
// =====================================================================
__global__ __launch_bounds__(1024)
void rn_head_kernel(const float* __restrict__ qst,
                    const float* __restrict__ W4, const float* __restrict__ b4,
                    const float* __restrict__ W5, const float* __restrict__ b5,
                    const float* __restrict__ W6, const float* __restrict__ b6,
                    float* __restrict__ out) {
    __shared__ float red[1024];
    __shared__ __align__(16) float hin[H_ + QST_];
    __shared__ __align__(16) float h4[H_];
    __shared__ __align__(16) float h5[H_];
    __shared__ float logits[NANS];
    const int b = blockIdx.x, tid = threadIdx.x;
    const int w = tid >> 5, lane = tid & 31;

    {
        const int c = tid & 511, hh = tid >> 9;
        const float* pp = g_part + ((size_t)b * D_ + hh * 32) * H_ + c;
        float s = 0.f;
#pragma unroll 8
        for (int r = 0; r < 32; ++r) s += pp[r * H_];
        red[tid] = s;
    }
    __syncthreads();
    if (tid < H_) hin[tid] = red[tid] + red[tid + 512];
    else if (tid < H_ + QST_) hin[tid] = qst[b * QST_ + (tid - H_)];
    __syncthreads();

    for (int k = 0; k < 16; ++k) {                        // layer 4: 768 -> 512
        const int o = w * 16 + k;
        const float4* wr = (const float4*)(W4 + (size_t)o * (H_ + QST_));
        const float4* hv = (const float4*)hin;
        float a = 0.f;
#pragma unroll
        for (int m = 0; m < 6; ++m) {
            float4 x4 = wr[lane + 32 * m], y4 = hv[lane + 32 * m];
            a += x4.x * y4.x + x4.y * y4.y + x4.z * y4.z + x4.w * y4.w;
        }
#pragma unroll
        for (int off = 16; off; off >>= 1) a += __shfl_xor_sync(0xffffffffu, a, off);
        if (lane == 0) { float t = a + b4[o]; h4[o] = t > 0.f ? t : 0.f; }
    }
    __syncthreads();

    for (int k = 0; k < 16; ++k) {                        // layer 5: 512 -> 512
        const int o = w * 16 + k;
        const float4* wr = (const float4*)(W5 + (size_t)o * H_);
        const float4* hv = (const float4*)h4;
        float a = 0.f;
#pragma unroll
        for (int m = 0; m < 4; ++m) {
            float4 x4 = wr[lane + 32 * m], y4 = hv[lane + 32 * m];
            a += x4.x * y4.x + x4.y * y4.y + x4.z * y4.z + x4.w * y4.w;
        }
#pragma unroll
        for (int off = 16; off; off >>= 1) a += __shfl_xor_sync(0xffffffffu, a, off);
        if (lane == 0) { float t = a + b5[o]; h5[o] = t > 0.f ? t : 0.f; }
    }
    __syncthreads();

    if (w < NANS) {                                       // layer 6: 512 -> 28
        const float4* wr = (const float4*)(W6 + (size_t)w * H_);
        const float4* hv = (const float4*)h5;
        float a = 0.f;
#pragma unroll
        for (int m = 0; m < 4; ++m) {
            float4 x4 = wr[lane + 32 * m], y4 = hv[lane + 32 * m];
            a += x4.x * y4.x + x4.y * y4.y + x4.z * y4.z + x4.w * y4.w;
        }
#pragma unroll
        for (int off = 16; off; off >>= 1) a += __shfl_xor_sync(0xffffffffu, a, off);
        if (lane == 0) logits[w] = a + b6[w];
    }
    __syncthreads();

    if (w == 0) {
        float z = lane < NANS ? logits[lane] : -INFINITY;
        float m = z;
#pragma unroll
        for (int off = 16; off; off >>= 1) m = fmaxf(m, __shfl_xor_sync(0xffffffffu, m, off));
        float e = lane < NANS ? expf(z - m) : 0.f;
        float s = e;
#pragma unroll
        for (int off = 16; off; off >>= 1) s += __shfl_xor_sync(0xffffffffu, s, off);
        if (lane < NANS) out[b * NANS + lane] = z - m - logf(s);
    }
}

// =====================================================================
extern "C" void kernel_launch(void* const* d_in, const int* in_sizes, int n_in,
                              void* d_out, int out_size) {
    const float* x   = (const float*)d_in[0];
    const float* qst = (const float*)d_in[1];
    const float* W0  = (const float*)d_in[2];
    const float* b0  = (const float*)d_in[3];
    const float* W1  = (const float*)d_in[4];
    const float* b1  = (const float*)d_in[5];
    const float* W2  = (const float*)d_in[6];
    const float* b2  = (const float*)d_in[7];
    const float* W3  = (const float*)d_in[8];
    const float* b3  = (const float*)d_in[9];
    const float* W4  = (const float*)d_in[10];
    const float* b4  = (const float*)d_in[11];
    const float* W5  = (const float*)d_in[12];
    const float* b5  = (const float*)d_in[13];
    const float* W6  = (const float*)d_in[14];
    const float* b6  = (const float*)d_in[15];
    float* out = (float*)d_out;

    const int smem_uv = (H_ * 52 + D_ * K_) * 4;
    cudaFuncSetAttribute(prep_uv,        cudaFuncAttributeMaxDynamicSharedMemorySize, smem_uv);
    cudaFuncSetAttribute(rn_pair_kernel, cudaFuncAttributeMaxDynamicSharedMemorySize, SMEM_PAIR);

    prep_uv<<<B_, 512, smem_uv>>>(x, W0, b0);
    prep_w<<<(3 * H_ * H_ + 255) / 256, 256>>>(W1, W2, W3);
    rn_pair_kernel<<<dim3(D_ / 2, B_), 512, SMEM_PAIR>>>(b1, b2, b3);
    rn_head_kernel<<<B_, 1024>>>(qst, W4, b4, W5, b5, W6, b6, out);
}